// round 1
// baseline (speedup 1.0000x reference)
#include <cuda_runtime.h>

// Problem: B=32, N=64, D=512
// score[b,i,j] = (dot(s_e[b,i,j,:], W) + bias) * adj[b,i,j]  (with adj[b,0,1]=adj[b,1,0]=0)
// Only i in {0,1} is ever consumed downstream.
// Outputs (flattened, float32, in tuple order):
//   final_id : (32,2)   -> 64 elements   [argmax indices as floats]
//   s_e_score: (32,2,64)-> 4096 elements
//   flag     : (32,)    -> 32 elements
// total 4192

#define NB 32
#define NN 64
#define ND 512

// One warp per (b, i, j) dot product. 32*2*64 = 4096 warps.
__global__ void score_kernel(const float* __restrict__ s_e,
                             const float* __restrict__ adj,
                             const float* __restrict__ W,
                             const float* __restrict__ bias,
                             float* __restrict__ out_score) {
    int gw = (blockIdx.x * blockDim.x + threadIdx.x) >> 5;
    int lane = threadIdx.x & 31;
    if (gw >= NB * 2 * NN) return;
    int b = gw >> 7;            // / 128
    int i = (gw >> 6) & 1;
    int j = gw & 63;

    // s_e[b, i, j, :] : contiguous 512 floats
    const float4* p  = (const float4*)(s_e + ((size_t)((b * NN + i) * NN + j)) * ND);
    const float4* wv = (const float4*)W;

    float sum = 0.f;
#pragma unroll
    for (int k = 0; k < 4; k++) {
        float4 a  = p[k * 32 + lane];
        float4 ww = wv[k * 32 + lane];
        sum += a.x * ww.x + a.y * ww.y + a.z * ww.z + a.w * ww.w;
    }
#pragma unroll
    for (int off = 16; off; off >>= 1)
        sum += __shfl_xor_sync(0xffffffffu, sum, off);

    if (lane == 0) {
        float a = adj[(b * NN + i) * NN + j];
        if ((i == 0 && j == 1) || (i == 1 && j == 0)) a = 0.f;
        out_score[(b * 2 + i) * NN + j] = (sum + bias[0]) * a;
    }
}

// One block, 64 threads: thread t handles row (b = t/2, i = t%2).
// Strict-> scan == JAX argmax first-occurrence-of-max semantics.
__global__ void argmax_flag_kernel(const float* __restrict__ score,
                                   float* __restrict__ out_id,
                                   float* __restrict__ out_flag) {
    __shared__ int ids[64];
    int t = threadIdx.x;   // 0..63 == b*2 + i
    const float* row = score + t * NN;
    float mx = row[0];
    int idx = 0;
#pragma unroll 8
    for (int j = 1; j < NN; j++) {
        float v = row[j];
        if (v > mx) { mx = v; idx = j; }
    }
    ids[t] = idx;
    out_id[t] = (float)idx;
    __syncthreads();
    if ((t & 1) == 0) {
        int sub = ids[t];
        int obj = ids[t + 1];
        float f = 0.f;
        if (sub > 0 && obj > 0)      f = 3.f;
        else if (sub > 0)            f = 1.f;
        else if (obj > 0)            f = 2.f;
        out_flag[t >> 1] = f;
    }
}

extern "C" void kernel_launch(void* const* d_in, const int* in_sizes, int n_in,
                              void* d_out, int out_size) {
    const float* s_e  = (const float*)d_in[0];
    const float* adj  = (const float*)d_in[1];
    const float* W    = (const float*)d_in[2];
    const float* bias = (const float*)d_in[3];

    float* out       = (float*)d_out;
    float* out_id    = out;            // 64
    float* out_score = out + 64;       // 4096
    float* out_flag  = out + 64 + 4096;// 32

    // 4096 warps, 8 warps/block -> 512 blocks
    score_kernel<<<512, 256>>>(s_e, adj, W, bias, out_score);
    argmax_flag_kernel<<<1, 64>>>(out_score, out_id, out_flag);
}

// round 2
// speedup vs baseline: 1.2657x; 1.2657x over previous
#include <cuda_runtime.h>

// B=32, N=64, D=512
// score[b,i,j] = (dot(s_e[b,i,j,:], W) + bias) * adj[b,i,j], adj[b,0,1]=adj[b,1,0]=0
// Only i in {0,1} consumed. Outputs (float32, flattened tuple order):
//   final_id (32,2)=64 | s_e_score (32,2,64)=4096 | flag (32)=32

#define NB 32
#define NN 64
#define ND 512

__global__ void __launch_bounds__(512, 1)
fused_kernel(const float* __restrict__ s_e,
             const float* __restrict__ adj,
             const float* __restrict__ W,
             const float* __restrict__ bias,
             float* __restrict__ out_id,
             float* __restrict__ out_score,
             float* __restrict__ out_flag) {
    int b    = blockIdx.x;
    int warp = threadIdx.x >> 5;
    int lane = threadIdx.x & 31;

    __shared__ float s_score[2][NN];
    __shared__ int   s_ids[2];

    // Cache W (512 floats) across the warp: 4 float4 per lane.
    const float4* wv = (const float4*)W;
    float4 w0 = wv[lane], w1 = wv[32 + lane], w2 = wv[64 + lane], w3 = wv[96 + lane];
    float bias0 = __ldg(bias);

    // 16 warps x 8 (i,j) pairs = 128 dot products of length 512.
    int p0 = warp * 8;
#pragma unroll 4
    for (int p = p0; p < p0 + 8; ++p) {
        int i = p >> 6;
        int j = p & 63;
        const float4* base =
            (const float4*)(s_e + ((size_t)((b * NN + i) * NN + j)) * ND);
        float4 a0 = base[lane];
        float4 a1 = base[32 + lane];
        float4 a2 = base[64 + lane];
        float4 a3 = base[96 + lane];

        float sum = a0.x * w0.x + a0.y * w0.y + a0.z * w0.z + a0.w * w0.w
                  + a1.x * w1.x + a1.y * w1.y + a1.z * w1.z + a1.w * w1.w
                  + a2.x * w2.x + a2.y * w2.y + a2.z * w2.z + a2.w * w2.w
                  + a3.x * w3.x + a3.y * w3.y + a3.z * w3.z + a3.w * w3.w;

#pragma unroll
        for (int off = 16; off; off >>= 1)
            sum += __shfl_xor_sync(0xffffffffu, sum, off);

        if (lane == 0) {
            float a = adj[(b * NN + i) * NN + j];
            if ((i == 0 && j == 1) || (i == 1 && j == 0)) a = 0.f;
            float sc = (sum + bias0) * a;
            s_score[i][j] = sc;
            out_score[(b * 2 + i) * NN + j] = sc;
        }
    }
    __syncthreads();

    // Warps 0 and 1: argmax over 64 values each (first-occurrence tie-break).
    if (warp < 2) {
        float v0 = s_score[warp][lane];
        float v1 = s_score[warp][lane + 32];
        float v; int idx;
        if (v1 > v0) { v = v1; idx = lane + 32; }
        else         { v = v0; idx = lane; }
#pragma unroll
        for (int off = 16; off; off >>= 1) {
            float ov = __shfl_xor_sync(0xffffffffu, v, off);
            int   oi = __shfl_xor_sync(0xffffffffu, idx, off);
            if (ov > v || (ov == v && oi < idx)) { v = ov; idx = oi; }
        }
        if (lane == 0) {
            s_ids[warp] = idx;
            out_id[b * 2 + warp] = (float)idx;
        }
    }
    __syncthreads();

    if (threadIdx.x == 0) {
        int sub = s_ids[0];
        int obj = s_ids[1];
        float f = 0.f;
        if (sub > 0 && obj > 0)      f = 3.f;
        else if (sub > 0)            f = 1.f;
        else if (obj > 0)            f = 2.f;
        out_flag[b] = f;
    }
}

extern "C" void kernel_launch(void* const* d_in, const int* in_sizes, int n_in,
                              void* d_out, int out_size) {
    const float* s_e  = (const float*)d_in[0];
    const float* adj  = (const float*)d_in[1];
    const float* W    = (const float*)d_in[2];
    const float* bias = (const float*)d_in[3];

    float* out       = (float*)d_out;
    float* out_id    = out;             // 64
    float* out_score = out + 64;        // 4096
    float* out_flag  = out + 64 + 4096; // 32

    fused_kernel<<<NB, 512>>>(s_e, adj, W, bias, out_id, out_score, out_flag);
}